// round 5
// baseline (speedup 1.0000x reference)
#include <cuda_runtime.h>
#include <cuda_fp16.h>
#include <cstdint>

#define B_ 2
#define L_ 512
#define V_ 64
#define D_ 128
#define NC_ 8

// ---- static device scratch (no allocations allowed) ----
__device__ float g_sumK[B_ * L_ * D_];
__device__ int   g_idx[B_][NC_][L_];
__device__ int   g_cnt[B_][NC_];

// ===========================================================================
// Kernel 1: sumK[b,l,d] = sum_v key[b,l,v,d]  (v split 4-way, MLP=16)
// ===========================================================================
__global__ void sumk_kernel(const float4* __restrict__ key4) {
    __shared__ float4 part[128];
    int bl = blockIdx.x;
    int g = threadIdx.x & 31, q = threadIdx.x >> 5;
    const float4* p = key4 + (size_t)bl * (V_ * D_ / 4) + (size_t)(q * 16) * (D_ / 4) + g;
    float4 s = make_float4(0.f, 0.f, 0.f, 0.f);
#pragma unroll
    for (int v = 0; v < 16; v++) {
        float4 t = p[(size_t)v * (D_ / 4)];
        s.x += t.x; s.y += t.y; s.z += t.z; s.w += t.w;
    }
    part[threadIdx.x] = s;
    __syncthreads();
    if (q == 0) {
        float4 a = part[g], b2 = part[32 + g], c2 = part[64 + g], d2 = part[96 + g];
        ((float4*)g_sumK)[(size_t)bl * 32 + g] =
            make_float4(a.x + b2.x + c2.x + d2.x, a.y + b2.y + c2.y + d2.y,
                        a.z + b2.z + c2.z + d2.z, a.w + b2.w + c2.w + d2.w);
    }
}

// ===========================================================================
// Kernel 2: deterministic per-(b,c) index lists via ballot compaction
// ===========================================================================
__global__ void build_idx_kernel(const int* __restrict__ label) {
    int c = blockIdx.x, b = blockIdx.y;
    int lane = threadIdx.x;
    int cnt = 0;
    for (int l0 = 0; l0 < L_; l0 += 32) {
        int l = l0 + lane;
        int lbl = label[b * L_ + l];
        unsigned m = __ballot_sync(0xffffffffu, lbl == c);
        if (lbl == c) {
            int pos = cnt + __popc(m & ((1u << lane) - 1u));
            g_idx[b][c][pos] = l;
        }
        cnt += __popc(m);
    }
    if (lane == 0) g_cnt[b][c] = cnt;
}

// ===========================================================================
// mma.sync / ldmatrix helpers (family-common PTX, valid on target sm_103)
// ===========================================================================
__device__ __forceinline__ uint32_t smem_u32(const void* p) {
    uint32_t a;
    asm("{ .reg .u64 t; cvta.to.shared.u64 t, %1; cvt.u32.u64 %0, t; }"
        : "=r"(a) : "l"(p));
    return a;
}
__device__ __forceinline__ void ldsm4(uint32_t addr, uint32_t* r) {
    asm volatile("ldmatrix.sync.aligned.m8n8.x4.shared.b16 {%0,%1,%2,%3}, [%4];"
                 : "=r"(r[0]), "=r"(r[1]), "=r"(r[2]), "=r"(r[3]) : "r"(addr));
}
__device__ __forceinline__ void ldsm4t(uint32_t addr, uint32_t* r) {
    asm volatile("ldmatrix.sync.aligned.m8n8.x4.trans.shared.b16 {%0,%1,%2,%3}, [%4];"
                 : "=r"(r[0]), "=r"(r[1]), "=r"(r[2]), "=r"(r[3]) : "r"(addr));
}
__device__ __forceinline__ void mma16816(float* c, const uint32_t* a,
                                         uint32_t b0, uint32_t b1) {
    asm volatile(
        "mma.sync.aligned.m16n8k16.row.col.f32.f16.f16.f32 "
        "{%0,%1,%2,%3}, {%4,%5,%6,%7}, {%8,%9}, {%0,%1,%2,%3};"
        : "+f"(c[0]), "+f"(c[1]), "+f"(c[2]), "+f"(c[3])
        : "r"(a[0]), "r"(a[1]), "r"(a[2]), "r"(a[3]), "r"(b0), "r"(b1));
}
// fp16 split: x = hi + lo, hi*hi exact in fp32; dropped lo*lo ~2^-22 rel
__device__ __forceinline__ void split2(float x0, float x1,
                                       uint32_t& hi, uint32_t& lo) {
    __half h0 = __float2half_rn(x0), h1 = __float2half_rn(x1);
    __half l0 = __float2half_rn(x0 - __half2float(h0));
    __half l1 = __float2half_rn(x1 - __half2float(h1));
    __half2 hp = __halves2half2(h0, h1), lp = __halves2half2(l0, l1);
    hi = *reinterpret_cast<uint32_t*>(&hp);
    lo = *reinterpret_cast<uint32_t*>(&lp);
}
// byte offset in a 128x128 f16 tile, 256B rows, 16B-chunk XOR swizzle
__device__ __forceinline__ uint32_t swz(int row, int col) {
    return (uint32_t)(row * 256) + (uint32_t)((((col >> 3) ^ (row & 7)) & 15) << 4)
         + (uint32_t)((col & 7) << 1);
}

// smem layout (bytes): 6 f16 tiles of 32KB + idx
#define SM_QHI  0
#define SM_QLO  32768
#define SM_KHI  65536
#define SM_KLO  98304
#define SM_VHI  131072
#define SM_VLO  163840
#define SM_IDX  196608
#define SMEM_TOTAL 198656

// Dead-code-in-practice fallback for nc > 128 (slow, simple, correct).
__device__ __noinline__ void attn_fallback(int b, int c, int k, int nc,
                                           const int* idxs,
                                           const float* query,
                                           const float* value,
                                           float* out) {
    const float scale = 0.08838834764831845f;
    for (int r = threadIdx.x; r < nc; r += blockDim.x) {
        int i = idxs[r];
        const float* q = query + (((size_t)b * L_ + i) * V_ + k) * D_;
        float m = -1e30f;
        for (int jj = 0; jj < nc; jj++) {
            const float* kr = g_sumK + ((size_t)b * L_ + idxs[jj]) * D_;
            float s = 0.f;
            for (int d = 0; d < D_; d++) s += q[d] * kr[d];
            m = fmaxf(m, s * scale);
        }
        float l = 0.f;
        for (int jj = 0; jj < nc; jj++) {
            const float* kr = g_sumK + ((size_t)b * L_ + idxs[jj]) * D_;
            float s = 0.f;
            for (int d = 0; d < D_; d++) s += q[d] * kr[d];
            l += __expf(s * scale - m);
        }
        for (int d0 = 0; d0 < D_; d0 += 32) {
            float acc[32];
            for (int e = 0; e < 32; e++) acc[e] = 0.f;
            for (int jj = 0; jj < nc; jj++) {
                const float* kr = g_sumK + ((size_t)b * L_ + idxs[jj]) * D_;
                float s = 0.f;
                for (int d = 0; d < D_; d++) s += q[d] * kr[d];
                float p = __expf(s * scale - m) / l;
                const float* vr = value +
                    (((size_t)b * L_ + idxs[jj]) * V_ + k) * D_ + d0;
                for (int e = 0; e < 32; e++) acc[e] += p * vr[e];
            }
            float* dst = out + (((size_t)b * L_ + i) * V_ + k) * D_ + d0;
            for (int e = 0; e < 32; e++) dst[e] = acc[e];
        }
    }
}

// ===========================================================================
// Kernel 3: tensor-core (HMMA) clustered attention. CTA = (head k, cluster, b)
// ===========================================================================
extern __shared__ char smx[];

__global__ __launch_bounds__(256, 1)
void attn_mma_kernel(const float* __restrict__ query,
                     const float* __restrict__ value,
                     float* __restrict__ out) {
    const int k = blockIdx.x, c = blockIdx.y, b = blockIdx.z;
    const int tid = threadIdx.x;
    const int lane = tid & 31;
    const int w = tid >> 5;
    const float scale = 0.08838834764831845f;

    const int nc = g_cnt[b][c];
    if (nc == 0) return;
    int* idxs = (int*)(smx + SM_IDX);
    for (int t = tid; t < nc; t += 256) idxs[t] = g_idx[b][c][t];
    __syncthreads();
    if (nc > 128) { attn_fallback(b, c, k, nc, idxs, query, value, out); return; }

    const int nr = (nc + 15) & ~15;     // rows zero-padded to 16

    // ---- gather + fp16-split conversion into smem tiles ------------------
    for (int t = tid; t < nr * 64; t += 256) {     // 64 float2 per row
        int row = t >> 6, cp = t & 63;
        float2 x = make_float2(0.f, 0.f);
        if (row < nc)
            x = ((const float2*)query)[
                    ((((size_t)b * L_ + idxs[row]) * V_ + k) << 6) + cp];
        uint32_t hi, lo;
        split2(x.x * scale, x.y * scale, hi, lo);
        uint32_t off = swz(row, cp << 1);
        *(uint32_t*)(smx + SM_QHI + off) = hi;
        *(uint32_t*)(smx + SM_QLO + off) = lo;
    }
    for (int t = tid; t < nr * 64; t += 256) {
        int row = t >> 6, cp = t & 63;
        float2 x = make_float2(0.f, 0.f);
        if (row < nc)
            x = ((const float2*)g_sumK)[(((size_t)b * L_ + idxs[row]) << 6) + cp];
        uint32_t hi, lo;
        split2(x.x, x.y, hi, lo);
        uint32_t off = swz(row, cp << 1);
        *(uint32_t*)(smx + SM_KHI + off) = hi;
        *(uint32_t*)(smx + SM_KLO + off) = lo;
    }
    for (int t = tid; t < nr * 64; t += 256) {
        int row = t >> 6, cp = t & 63;
        float2 x = make_float2(0.f, 0.f);
        if (row < nc)
            x = ((const float2*)value)[
                    ((((size_t)b * L_ + idxs[row]) * V_ + k) << 6) + cp];
        uint32_t hi, lo;
        split2(x.x, x.y, hi, lo);
        uint32_t off = swz(row, cp << 1);
        *(uint32_t*)(smx + SM_VHI + off) = hi;
        *(uint32_t*)(smx + SM_VLO + off) = lo;
    }
    __syncthreads();

    // ---- warp-level work: warp w owns S rows [16w, 16w+16) ----------------
    const int row0 = w * 16;
    if (row0 >= nc) return;    // no barriers after this point

    const uint32_t qhi = smem_u32(smx) + SM_QHI;
    const uint32_t qlo = qhi + 32768;
    const uint32_t khi = qhi + 65536;
    const uint32_t klo = qhi + 98304;
    const uint32_t vhi = qhi + 131072;
    const uint32_t vlo = qhi + 163840;

    const int g = lane >> 3;
    const int rA = (lane & 7) + ((g & 1) << 3);        // A / V-trans row offset
    const int cA = ((g >> 1) & 1) << 3;
    const int rB = (lane & 7) + (((g >> 1) & 1) << 3); // B (K) row offset
    const int cB = (g & 1) << 3;

    const int npair = (nc + 15) >> 4;   // 16-wide col / k groups

    // ================= S = Q * Ksum^T ====================
    float cS[16][4];
#pragma unroll
    for (int n = 0; n < 16; n++)
#pragma unroll
        for (int r = 0; r < 4; r++) cS[n][r] = 0.f;

#pragma unroll
    for (int s = 0; s < 8; s++) {
        uint32_t ah[4], al[4];
        ldsm4(qhi + swz(row0 + rA, s * 16 + cA), ah);
        ldsm4(qlo + swz(row0 + rA, s * 16 + cA), al);
#pragma unroll
        for (int p = 0; p < 8; p++) {
            if (p < npair) {
                uint32_t bh[4], bl[4];
                ldsm4(khi + swz(16 * p + rB, s * 16 + cB), bh);
                ldsm4(klo + swz(16 * p + rB, s * 16 + cB), bl);
                mma16816(cS[2 * p],     ah, bh[0], bh[1]);
                mma16816(cS[2 * p],     ah, bl[0], bl[1]);
                mma16816(cS[2 * p],     al, bh[0], bh[1]);
                mma16816(cS[2 * p + 1], ah, bh[2], bh[3]);
                mma16816(cS[2 * p + 1], ah, bl[2], bl[3]);
                mma16816(cS[2 * p + 1], al, bh[2], bh[3]);
            }
        }
    }

    // ================= warp-local softmax =================
    const int colb = (lane & 3) << 1;   // base col within 8-tile
    float m0 = -1e30f, m1 = -1e30f;
#pragma unroll
    for (int n = 0; n < 16; n++) {
        if (n < 2 * npair) {
            int c0 = n * 8 + colb;
            if (c0 < nc)     { m0 = fmaxf(m0, cS[n][0]); m1 = fmaxf(m1, cS[n][2]); }
            if (c0 + 1 < nc) { m0 = fmaxf(m0, cS[n][1]); m1 = fmaxf(m1, cS[n][3]); }
        }
    }
    m0 = fmaxf(m0, __shfl_xor_sync(0xffffffffu, m0, 1));
    m0 = fmaxf(m0, __shfl_xor_sync(0xffffffffu, m0, 2));
    m1 = fmaxf(m1, __shfl_xor_sync(0xffffffffu, m1, 1));
    m1 = fmaxf(m1, __shfl_xor_sync(0xffffffffu, m1, 2));

    float l0 = 0.f, l1 = 0.f;
    uint32_t phi[8][4], plo[8][4];
#pragma unroll
    for (int kt = 0; kt < 8; kt++) {
        if (kt < npair) {
            float pv[8];
#pragma unroll
            for (int u = 0; u < 2; u++) {           // n-tiles 2kt, 2kt+1
                int n = 2 * kt + u;
                int c0 = n * 8 + colb;
                pv[4 * u + 0] = (c0     < nc) ? __expf(cS[n][0] - m0) : 0.f;
                pv[4 * u + 1] = (c0 + 1 < nc) ? __expf(cS[n][1] - m0) : 0.f;
                pv[4 * u + 2] = (c0     < nc) ? __expf(cS[n][2] - m1) : 0.f;
                pv[4 * u + 3] = (c0 + 1 < nc) ? __expf(cS[n][3] - m1) : 0.f;
            }
            l0 += pv[0] + pv[1] + pv[4] + pv[5];
            l1 += pv[2] + pv[3] + pv[6] + pv[7];
            // pack into A-fragments: a0=(r,c) a1=(r+8,c) a2=(r,c+8) a3=(r+8,c+8)
            split2(pv[0], pv[1], phi[kt][0], plo[kt][0]);
            split2(pv[2], pv[3], phi[kt][1], plo[kt][1]);
            split2(pv[4], pv[5], phi[kt][2], plo[kt][2]);
            split2(pv[6], pv[7], phi[kt][3], plo[kt][3]);
        }
    }
    l0 += __shfl_xor_sync(0xffffffffu, l0, 1);
    l0 += __shfl_xor_sync(0xffffffffu, l0, 2);
    l1 += __shfl_xor_sync(0xffffffffu, l1, 1);
    l1 += __shfl_xor_sync(0xffffffffu, l1, 2);

    // ================= O = P * V ====================
    float o[16][4];
#pragma unroll
    for (int n = 0; n < 16; n++)
#pragma unroll
        for (int r = 0; r < 4; r++) o[n][r] = 0.f;

#pragma unroll
    for (int kt = 0; kt < 8; kt++) {
        if (kt < npair) {
#pragma unroll
            for (int dp = 0; dp < 8; dp++) {
                uint32_t vh[4], vl[4];
                ldsm4t(vhi + swz(16 * kt + rA, 16 * dp + cA), vh);
                ldsm4t(vlo + swz(16 * kt + rA, 16 * dp + cA), vl);
                mma16816(o[2 * dp],     phi[kt], vh[0], vh[1]);
                mma16816(o[2 * dp],     phi[kt], vl[0], vl[1]);
                mma16816(o[2 * dp],     plo[kt], vh[0], vh[1]);
                mma16816(o[2 * dp + 1], phi[kt], vh[2], vh[3]);
                mma16816(o[2 * dp + 1], phi[kt], vl[2], vl[3]);
                mma16816(o[2 * dp + 1], plo[kt], vh[2], vh[3]);
            }
        }
    }

    // ================= epilogue ====================
    const int rlo = row0 + (lane >> 2);
    const int rhi = rlo + 8;
    const float i0 = 1.f / l0, i1 = 1.f / l1;
    float* dlo = (rlo < nc)
        ? out + (((size_t)b * L_ + idxs[rlo]) * V_ + k) * D_ : nullptr;
    float* dhi = (rhi < nc)
        ? out + (((size_t)b * L_ + idxs[rhi]) * V_ + k) * D_ : nullptr;
#pragma unroll
    for (int n = 0; n < 16; n++) {
        int col = n * 8 + colb;
        if (dlo) *(float2*)(dlo + col) = make_float2(o[n][0] * i0, o[n][1] * i0);
        if (dhi) *(float2*)(dhi + col) = make_float2(o[n][2] * i1, o[n][3] * i1);
    }
}

extern "C" void kernel_launch(void* const* d_in, const int* in_sizes, int n_in,
                              void* d_out, int out_size) {
    (void)in_sizes; (void)n_in; (void)out_size;
    const float* query = (const float*)d_in[0];
    const float* key   = (const float*)d_in[1];
    const float* value = (const float*)d_in[2];
    const int*   label = (const int*)d_in[3];
    float* out = (float*)d_out;

    sumk_kernel<<<B_ * L_, 128>>>((const float4*)key);
    build_idx_kernel<<<dim3(NC_, B_), 32>>>(label);
    cudaFuncSetAttribute(attn_mma_kernel,
                         cudaFuncAttributeMaxDynamicSharedMemorySize, SMEM_TOTAL);
    attn_mma_kernel<<<dim3(V_, NC_, B_), 256, SMEM_TOTAL>>>(query, value, out);
}